// round 16
// baseline (speedup 1.0000x reference)
#include <cuda_runtime.h>
#include <cuda_fp16.h>
#include <cstdint>
#include <math.h>

#define BB 128
#define TT 128
#define DD 300
#define HH 2048
#define H4 8192
#define KP1 320

// ---- device scratch (no allocation in kernel_launch) ----
__device__ float g_Zpre[(size_t)TT * BB * H4];   // x@W1 + bias, [t*BB+b][4H]
__device__ __half g_Xh[(size_t)TT * BB * KP1];    // x fp16, [r=t*BB+b][KP1]
__device__ __half g_W1h[(size_t)H4 * KP1];        // W[0:300,:]^T padded, [n][k], fp16
__device__ __half g_Whh[(size_t)H4 * HH];         // W[300:,:]^T, [n][k], fp16
__device__ __half g_hh[2][BB * HH];               // double-buffered h fp16
__device__ unsigned g_cnt = 0;                    // grid barrier
__device__ unsigned g_gen = 0;

// ---- helpers (base sm_100 ISA: cp.async + ldmatrix + mma.sync) ----
__device__ __forceinline__ uint32_t smem_u32(const void* p) {
    uint32_t a;
    asm("{ .reg .u64 t; cvta.to.shared.u64 t, %1; cvt.u32.u64 %0, t; }" : "=r"(a) : "l"(p));
    return a;
}
__device__ __forceinline__ void cpa16(uint32_t dst, const void* src) {
    asm volatile("cp.async.cg.shared.global [%0], [%1], 16;" :: "r"(dst), "l"(src) : "memory");
}
#define CP_COMMIT() asm volatile("cp.async.commit_group;" ::: "memory")
#define CP_WAIT1()  asm volatile("cp.async.wait_group 1;" ::: "memory")
#define CP_WAIT0()  asm volatile("cp.async.wait_group 0;" ::: "memory")

__device__ __forceinline__ void ldsm4(uint32_t* r, uint32_t addr) {
    asm volatile("ldmatrix.sync.aligned.m8n8.x4.shared.b16 {%0,%1,%2,%3}, [%4];"
                 : "=r"(r[0]), "=r"(r[1]), "=r"(r[2]), "=r"(r[3]) : "r"(addr));
}
__device__ __forceinline__ void mma_f16(float* c, const uint32_t* a,
                                        uint32_t b0, uint32_t b1) {
    asm volatile("mma.sync.aligned.m16n8k16.row.col.f32.f16.f16.f32 "
                 "{%0,%1,%2,%3}, {%4,%5,%6,%7}, {%8,%9}, {%0,%1,%2,%3};"
                 : "+f"(c[0]), "+f"(c[1]), "+f"(c[2]), "+f"(c[3])
                 : "r"(a[0]), "r"(a[1]), "r"(a[2]), "r"(a[3]), "r"(b0), "r"(b1));
}
__device__ __forceinline__ uint32_t sw128(uint32_t x) { return x ^ ((x >> 3) & 0x70); }

// smem: 3-stage GEMM buffer ring + separate Zpre stage; zs overlays the ring
#define OFF_A    0
#define OFF_B    8192
#define BUF_SZ   24576
#define ZPRE_OFF (3 * BUF_SZ)                  // 73728
#define SMEM_P1   (1024 + 3 * BUF_SZ)          // 74752
#define SMEM_PERS (1024 + 3 * BUF_SZ + 32768)  // 107520

// ---- activations (overflow-safe) ----
__device__ __forceinline__ float sigf(float x) {
    return __fdividef(1.f, 1.f + __expf(-x));
}
__device__ __forceinline__ float tanhfast(float x) {
    float e = __expf(-2.f * fabsf(x));
    return copysignf(__fdividef(1.f - e, 1.f + e), x);
}

// ---- grid barrier (all 128 CTAs resident; classic count+generation) ----
__device__ __forceinline__ void grid_sync()
{
    __syncthreads();
    if (threadIdx.x == 0) {
        __threadfence();
        unsigned gen = atomicAdd(&g_gen, 0u);       // read BEFORE arrival
        unsigned arrived = atomicAdd(&g_cnt, 1u);
        if (arrived == 127u) {
            g_cnt = 0;
            __threadfence();
            atomicAdd(&g_gen, 1u);
        } else {
            while (atomicAdd(&g_gen, 0u) == gen) __nanosleep(64);
        }
    }
    __syncthreads();
}

// ---- prep: X -> fp16 rows [r=t*BB+b][KP1], zero-padded K ----
__global__ void __launch_bounds__(KP1) convert_X(const float* __restrict__ X)
{
    int r = blockIdx.x, k = threadIdx.x;
    int t = r >> 7, b = r & (BB - 1);
    float v = (k < DD) ? X[((size_t)b * TT + t) * DD + k] : 0.f;
    g_Xh[(size_t)r * KP1 + k] = __float2half_rn(v);
}

// ---- prep: transpose W (fp16) into W1t [n][0..320) and Wht [n][0..2048) ----
__global__ void __launch_bounds__(256) transW(const float* __restrict__ W)
{
    __shared__ float tile[32][33];
    int tx = threadIdx.x, ty = threadIdx.y;   // 32 x 8
    int k_t = blockIdx.x * 32;                // 74 tiles over kk in [0,2368)
    int n_t = blockIdx.y * 32;
    #pragma unroll
    for (int i = 0; i < 4; i++) {
        int kk = k_t + ty + i * 8;
        float v = 0.f;
        if (kk < KP1) { if (kk < DD) v = W[(size_t)kk * H4 + n_t + tx]; }
        else           v = W[(size_t)(kk - 20) * H4 + n_t + tx];   // kk-320+300
        tile[ty + i * 8][tx] = v;
    }
    __syncthreads();
    #pragma unroll
    for (int i = 0; i < 4; i++) {
        int n  = n_t + ty + i * 8;
        int kk = k_t + tx;
        __half wh = __float2half_rn(tile[tx][ty + i * 8]);
        if (kk < KP1) g_W1h[(size_t)n * KP1 + kk] = wh;
        else          g_Whh[(size_t)n * HH + (kk - KP1)] = wh;
    }
}

// ---- GEMM compute for one chunk: 8 warps (2/SMSP), warp tile 32x32 ----
__device__ __forceinline__ void chunk_mma(uint32_t bp, int wm, int wn, int lane,
                                          float acc[2][4][4])
{
    #pragma unroll
    for (int ks = 0; ks < 4; ks++) {
        const uint32_t colb = (uint32_t)(ks * 32 + (lane >> 4) * 16);
        uint32_t a0[4], a1[4];
        ldsm4(a0, bp + OFF_A + sw128((uint32_t)((wm * 32 +      (lane & 15)) * 128) + colb));
        ldsm4(a1, bp + OFF_A + sw128((uint32_t)((wm * 32 + 16 + (lane & 15)) * 128) + colb));
        #pragma unroll
        for (int jp = 0; jp < 2; jp++) {
            uint32_t bf[4];
            ldsm4(bf, bp + OFF_B +
                  sw128((uint32_t)((wn * 32 + jp * 16 + (lane & 15)) * 128) + colb));
            mma_f16(acc[0][jp * 2 + 0], a0, bf[0], bf[2]);
            mma_f16(acc[1][jp * 2 + 0], a1, bf[0], bf[2]);
            mma_f16(acc[0][jp * 2 + 1], a0, bf[1], bf[3]);
            mma_f16(acc[1][jp * 2 + 1], a1, bf[1], bf[3]);
        }
    }
}

__device__ __forceinline__ void acc_to_zs(float* zs, int wm, int wn, int lane,
                                          float acc[2][4][4])
{
    #pragma unroll
    for (int i = 0; i < 2; i++)
        #pragma unroll
        for (int jj = 0; jj < 4; jj++)
            #pragma unroll
            for (int k4 = 0; k4 < 4; k4++) {
                int r = wm * 32 + i * 16 + (lane >> 2) + ((k4 >> 1) ? 8 : 0);
                int c = wn * 32 + jj * 8 + (lane & 3) * 2 + (k4 & 1);
                zs[r * 132 + c] = acc[i][jj][k4];
            }
}

// ---------------------------------------------------------------------------
// Phase 1: Zpre = X @ W1t^T + bias.  Tile M=64 x N=128, K=320 (5 chunks).
// 3-stage ring, one sync per chunk; warps 0-7 compute (32x32, 2m x 4n).
// ---------------------------------------------------------------------------
__global__ void __launch_bounds__(512, 1) phase1_kernel(const float* __restrict__ bias)
{
    extern __shared__ __align__(16) char dsm[];
    const uint32_t raw  = smem_u32(dsm);
    const uint32_t base = (raw + 1023) & ~1023u;
    float* zs = (float*)(dsm + (base - raw));      // reused post-GEMM, pitch 132

    const int tid = threadIdx.x, wid = tid >> 5, lane = tid & 31;
    const int wm = wid >> 2, wn = wid & 3;         // warps 0-7: 2m x 4n
    const int nb = blockIdx.x;
    const size_t r0 = (size_t)blockIdx.y * 64;

    // hoisted per-thread load addressing
    const int rowA = tid >> 3, q16 = (tid & 7) * 16;
    const uint32_t soA = OFF_A + sw128((uint32_t)(rowA * 128) + (uint32_t)q16);
    const char* gA = (const char*)(g_Xh + r0 * KP1) + (size_t)rowA * KP1 * 2 + q16;
    const int cB0 = tid >> 3, cB1 = cB0 + 64;
    const uint32_t soB0 = OFF_B + sw128((uint32_t)(cB0 * 128) + (uint32_t)q16);
    const uint32_t soB1 = OFF_B + sw128((uint32_t)(cB1 * 128) + (uint32_t)q16);
    const char* gB0 = (const char*)g_W1h + (size_t)(nb * 128 + cB0) * KP1 * 2 + q16;
    const char* gB1 = (const char*)g_W1h + (size_t)(nb * 128 + cB1) * KP1 * 2 + q16;

    auto load_chunk = [&](int j) {
        uint32_t bp = base + (j % 3) * BUF_SZ;
        int kb = j * 128;
        cpa16(bp + soA,  gA  + kb);
        cpa16(bp + soB0, gB0 + kb);
        cpa16(bp + soB1, gB1 + kb);
    };

    float acc[2][4][4];
    #pragma unroll
    for (int i = 0; i < 2; i++)
        #pragma unroll
        for (int j = 0; j < 4; j++)
            #pragma unroll
            for (int k = 0; k < 4; k++) acc[i][j][k] = 0.f;

    load_chunk(0); CP_COMMIT();
    load_chunk(1); CP_COMMIT();
    for (int j = 0; j < 5; j++) {
        if (j + 2 < 5) { CP_WAIT1(); } else { CP_WAIT0(); }
        __syncthreads();
        if (j + 2 < 5) { load_chunk(j + 2); CP_COMMIT(); }
        if (wid < 8) chunk_mma(base + (j % 3) * BUF_SZ, wm, wn, lane, acc);
    }
    __syncthreads();

    if (wid < 8) acc_to_zs(zs, wm, wn, lane, acc);
    __syncthreads();

    int nl = tid & 127, rg = tid >> 7;
    int n0 = nb * 128;
    float bz = bias[n0 + nl];
    #pragma unroll 4
    for (int i = 0; i < 16; i++) {
        int rl = rg * 16 + i;
        g_Zpre[(r0 + rl) * H4 + n0 + nl] = zs[rl * 132 + nl] + bz;
    }
}

// ---------------------------------------------------------------------------
// Persistent step kernel: 128 CTAs (nb 0..63, bm 0..1), all T steps in one
// launch with software grid barriers. c in registers; Zpre prefetched to smem;
// 3-stage ring, one sync per chunk; all load addressing hoisted.
// ---------------------------------------------------------------------------
__global__ void __launch_bounds__(512, 1) lstm_persistent(float* __restrict__ out)
{
    extern __shared__ __align__(16) char dsm[];
    const uint32_t raw  = smem_u32(dsm);
    const uint32_t base = (raw + 1023) & ~1023u;
    float* zs  = (float*)(dsm + (base - raw));               // pitch 132, post-GEMM
    float* zps = (float*)(dsm + (base - raw) + ZPRE_OFF);    // Zpre stage, pitch 128

    const int tid = threadIdx.x, wid = tid >> 5, lane = tid & 31;
    const int wm = wid >> 2, wn = wid & 3;         // warps 0-7: 2m x 4n
    const int nb = blockIdx.x >> 1;            // 0..63
    const int bm = blockIdx.x & 1;             // 0..1
    const int nl = lane;
    const int n  = nb * 32 + nl;

    // hoisted per-thread load addressing (step-invariant)
    const int rowA = tid >> 3, q16 = (tid & 7) * 16;
    const uint32_t soA = OFF_A + sw128((uint32_t)(rowA * 128) + (uint32_t)q16);
    const size_t offA = (size_t)(bm * 64 + rowA) * HH * 2 + q16;
    const char* gA0 = (const char*)g_hh[0] + offA;
    const char* gA1 = (const char*)g_hh[1] + offA;
    const int cB0 = tid >> 3, cB1 = cB0 + 64;
    const uint32_t soB0 = OFF_B + sw128((uint32_t)(cB0 * 128) + (uint32_t)q16);
    const uint32_t soB1 = OFF_B + sw128((uint32_t)(cB1 * 128) + (uint32_t)q16);
    const char* gB0 = (const char*)g_Whh
        + (size_t)((cB0 >> 5) * HH + nb * 32 + (cB0 & 31)) * HH * 2 + q16;
    const char* gB1 = (const char*)g_Whh
        + (size_t)((cB1 >> 5) * HH + nb * 32 + (cB1 & 31)) * HH * 2 + q16;
    // Zpre prefetch addressing (per step: advance by BB*H4*4 bytes)
    const int zrow = tid >> 2, zu = tid & 3;       // 512 thr x 4 iters covers 64x512B
    uint32_t zdst[4]; size_t zsrc_off[4];
    #pragma unroll
    for (int i = 0; i < 4; i++) {
        int e = tid + i * 512;
        int row = e >> 5, u = e & 31;
        zdst[i] = base + ZPRE_OFF + (uint32_t)(row * 512 + u * 16);
        zsrc_off[i] = (((size_t)bm * 64 + row) * H4
                       + (size_t)(u >> 3) * HH + nb * 32) * 4 + (u & 7) * 16;
    }
    (void)zrow; (void)zu;

    // ---- step 0 (no GEMM): c0 = i*g, h0 = o*tanh(c0); seed g_hh[0] ----
    float c_reg[4];
    #pragma unroll
    for (int it = 0; it < 4; it++) {
        int bl = wid + it * 16;
        int b  = bm * 64 + bl;
        const float* zp = g_Zpre + (size_t)b * H4;
        float cn = sigf(zp[n]) * tanhfast(zp[2 * HH + n]);
        float h  = sigf(zp[3 * HH + n]) * tanhfast(cn);
        c_reg[it] = cn;
        out[(size_t)b * TT * HH + n] = h;
        g_hh[0][b * HH + n] = __float2half_rn(h);
    }
    grid_sync();

    for (int t = 1; t < TT; t++) {
        const char* gA = ((t - 1) & 1) ? gA1 : gA0;

        auto load_chunk = [&](int j) {
            uint32_t bp = base + (j % 3) * BUF_SZ;
            int kb = j * 128;
            cpa16(bp + soA,  gA  + kb);
            cpa16(bp + soB0, gB0 + kb);
            cpa16(bp + soB1, gB1 + kb);
        };

        float acc[2][4][4];
        #pragma unroll
        for (int i = 0; i < 2; i++)
            #pragma unroll
            for (int j = 0; j < 4; j++)
                #pragma unroll
                for (int k = 0; k < 4; k++) acc[i][j][k] = 0.f;

        // chunk 0 + Zpre prefetch share the first commit group
        load_chunk(0);
        {
            const char* zsrc = (const char*)g_Zpre + (size_t)t * BB * H4 * 4;
            #pragma unroll
            for (int i = 0; i < 4; i++)
                cpa16(zdst[i], zsrc + zsrc_off[i]);
        }
        CP_COMMIT();
        load_chunk(1); CP_COMMIT();

        for (int j = 0; j < 32; j++) {
            if (j + 2 < 32) { CP_WAIT1(); } else { CP_WAIT0(); }
            __syncthreads();
            if (j + 2 < 32) { load_chunk(j + 2); CP_COMMIT(); }
            if (wid < 8) chunk_mma(base + (j % 3) * BUF_SZ, wm, wn, lane, acc);
        }
        __syncthreads();

        if (wid < 8) acc_to_zs(zs, wm, wn, lane, acc);
        __syncthreads();

        // fused epilogue: smem Zpre + register c
        #pragma unroll
        for (int it = 0; it < 4; it++) {
            int bl = wid + it * 16;
            int b  = bm * 64 + bl;
            const float* zr = zps + bl * 128;
            float vi = zs[bl * 132 +  0 + nl] + zr[ 0 + nl];
            float vf = zs[bl * 132 + 32 + nl] + zr[32 + nl];
            float vg = zs[bl * 132 + 64 + nl] + zr[64 + nl];
            float vo = zs[bl * 132 + 96 + nl] + zr[96 + nl];
            float ig = sigf(vi), fg = sigf(vf);
            float gg = tanhfast(vg), og = sigf(vo);
            float cn = fg * c_reg[it] + ig * gg;
            c_reg[it] = cn;
            float h = og * tanhfast(cn);
            out[(size_t)b * TT * HH + (size_t)t * HH + n] = h;
            g_hh[t & 1][b * HH + n] = __float2half_rn(h);
        }
        grid_sync();
    }
}

// ---------------------------------------------------------------------------
extern "C" void kernel_launch(void* const* d_in, const int* in_sizes, int n_in,
                              void* d_out, int out_size)
{
    (void)in_sizes; (void)n_in; (void)out_size;
    const float* X    = (const float*)d_in[0];   // embed_words [B][T][D]
    const float* W    = (const float*)d_in[2];   // [D+H][4H]  (d_in[1]=lengths unused)
    const float* bias = (const float*)d_in[3];   // [4H]
    float* out        = (float*)d_out;           // [B][T][H]

    cudaFuncSetAttribute(phase1_kernel,   cudaFuncAttributeMaxDynamicSharedMemorySize, SMEM_P1);
    cudaFuncSetAttribute(lstm_persistent, cudaFuncAttributeMaxDynamicSharedMemorySize, SMEM_PERS);

    convert_X<<<TT * BB, KP1>>>(X);
    transW<<<dim3(74, 256), dim3(32, 8)>>>(W);
    phase1_kernel<<<dim3(64, 256), 512, SMEM_P1>>>(bias);
    lstm_persistent<<<128, 512, SMEM_PERS>>>(out);
}

// round 17
// speedup vs baseline: 1.1243x; 1.1243x over previous
#include <cuda_runtime.h>
#include <cuda_fp16.h>
#include <cstdint>
#include <math.h>

#define BB 128
#define TT 128
#define DD 300
#define HH 2048
#define H4 8192
#define KP1 320

// ---- device scratch (no allocation in kernel_launch) ----
__device__ float g_Zpre[(size_t)TT * BB * H4];   // x@W1 + bias, [t*BB+b][4H]
__device__ __half g_Xh[(size_t)TT * BB * KP1];    // x fp16, [r=t*BB+b][KP1]
__device__ __half g_W1h[(size_t)H4 * KP1];        // W[0:300,:]^T padded, [n][k], fp16
__device__ __half g_Whh[(size_t)H4 * HH];         // W[300:,:]^T, [n][k], fp16
__device__ __half g_hh[2][BB * HH];               // double-buffered h fp16
__device__ unsigned g_cnt = 0;                    // grid barrier
__device__ unsigned g_gen = 0;

// ---- helpers (base sm_100 ISA: cp.async + ldmatrix + mma.sync) ----
__device__ __forceinline__ uint32_t smem_u32(const void* p) {
    uint32_t a;
    asm("{ .reg .u64 t; cvta.to.shared.u64 t, %1; cvt.u32.u64 %0, t; }" : "=r"(a) : "l"(p));
    return a;
}
__device__ __forceinline__ void cpa16(uint32_t dst, const void* src) {
    asm volatile("cp.async.cg.shared.global [%0], [%1], 16;" :: "r"(dst), "l"(src) : "memory");
}
#define CP_COMMIT() asm volatile("cp.async.commit_group;" ::: "memory")
#define CP_WAIT1()  asm volatile("cp.async.wait_group 1;" ::: "memory")
#define CP_WAIT0()  asm volatile("cp.async.wait_group 0;" ::: "memory")

__device__ __forceinline__ void ldsm4(uint32_t* r, uint32_t addr) {
    asm volatile("ldmatrix.sync.aligned.m8n8.x4.shared.b16 {%0,%1,%2,%3}, [%4];"
                 : "=r"(r[0]), "=r"(r[1]), "=r"(r[2]), "=r"(r[3]) : "r"(addr));
}
__device__ __forceinline__ void mma_f16(float* c, const uint32_t* a,
                                        uint32_t b0, uint32_t b1) {
    asm volatile("mma.sync.aligned.m16n8k16.row.col.f32.f16.f16.f32 "
                 "{%0,%1,%2,%3}, {%4,%5,%6,%7}, {%8,%9}, {%0,%1,%2,%3};"
                 : "+f"(c[0]), "+f"(c[1]), "+f"(c[2]), "+f"(c[3])
                 : "r"(a[0]), "r"(a[1]), "r"(a[2]), "r"(a[3]), "r"(b0), "r"(b1));
}
__device__ __forceinline__ uint32_t sw128(uint32_t x) { return x ^ ((x >> 3) & 0x70); }

// smem: double GEMM buffers + separate Zpre stage; zs overlaps GEMM buffers
#define OFF_A    0
#define OFF_B    8192
#define BUF_SZ   24576
#define ZPRE_OFF (2 * BUF_SZ)                  // 49152
#define SMEM_P1   (1024 + 2 * BUF_SZ)          // phase1: no zpre stage
#define SMEM_PERS (1024 + 2 * BUF_SZ + 32768)  // 82944

// ---- activations (overflow-safe) ----
__device__ __forceinline__ float sigf(float x) {
    return __fdividef(1.f, 1.f + __expf(-x));
}
__device__ __forceinline__ float tanhfast(float x) {
    float e = __expf(-2.f * fabsf(x));
    return copysignf(__fdividef(1.f - e, 1.f + e), x);
}

// ---- grid barrier (all 128 CTAs resident; classic count+generation) ----
__device__ __forceinline__ void grid_sync()
{
    __syncthreads();
    if (threadIdx.x == 0) {
        __threadfence();
        unsigned gen = atomicAdd(&g_gen, 0u);       // read BEFORE arrival
        unsigned arrived = atomicAdd(&g_cnt, 1u);
        if (arrived == 127u) {
            g_cnt = 0;
            __threadfence();
            atomicAdd(&g_gen, 1u);
        } else {
            while (atomicAdd(&g_gen, 0u) == gen) __nanosleep(64);
        }
    }
    __syncthreads();
}

// ---- prep: X -> fp16 rows [r=t*BB+b][KP1], zero-padded K ----
__global__ void __launch_bounds__(KP1) convert_X(const float* __restrict__ X)
{
    int r = blockIdx.x, k = threadIdx.x;
    int t = r >> 7, b = r & (BB - 1);
    float v = (k < DD) ? X[((size_t)b * TT + t) * DD + k] : 0.f;
    g_Xh[(size_t)r * KP1 + k] = __float2half_rn(v);
}

// ---- prep: transpose W (fp16) into W1t [n][0..320) and Wht [n][0..2048) ----
__global__ void __launch_bounds__(256) transW(const float* __restrict__ W)
{
    __shared__ float tile[32][33];
    int tx = threadIdx.x, ty = threadIdx.y;   // 32 x 8
    int k_t = blockIdx.x * 32;                // 74 tiles over kk in [0,2368)
    int n_t = blockIdx.y * 32;
    #pragma unroll
    for (int i = 0; i < 4; i++) {
        int kk = k_t + ty + i * 8;
        float v = 0.f;
        if (kk < KP1) { if (kk < DD) v = W[(size_t)kk * H4 + n_t + tx]; }
        else           v = W[(size_t)(kk - 20) * H4 + n_t + tx];   // kk-320+300
        tile[ty + i * 8][tx] = v;
    }
    __syncthreads();
    #pragma unroll
    for (int i = 0; i < 4; i++) {
        int n  = n_t + ty + i * 8;
        int kk = k_t + tx;
        __half wh = __float2half_rn(tile[tx][ty + i * 8]);
        if (kk < KP1) g_W1h[(size_t)n * KP1 + kk] = wh;
        else          g_Whh[(size_t)n * HH + (kk - KP1)] = wh;
    }
}

// ---- GEMM compute for one chunk: 8 warps (2/SMSP), warp tile 32x32 ----
// ldsm addressing collapsed: sw128(row*128+colb) = row*128 + (colb ^ (row&7)*16)
// -> per-thread precomputed bases + one XOR per ks.
__device__ __forceinline__ void chunk_mma(uint32_t bp, uint32_t a0b, uint32_t a1b,
                                          uint32_t b0b, uint32_t b1b, uint32_t cxv,
                                          float acc[2][4][4])
{
    #pragma unroll
    for (int ks = 0; ks < 4; ks++) {
        const uint32_t cs = ((uint32_t)(ks * 32)) ^ cxv;
        uint32_t a0[4], a1[4];
        ldsm4(a0, bp + a0b + cs);
        ldsm4(a1, bp + a1b + cs);
        #pragma unroll
        for (int jp = 0; jp < 2; jp++) {
            uint32_t bf[4];
            ldsm4(bf, bp + (jp ? b1b : b0b) + cs);
            mma_f16(acc[0][jp * 2 + 0], a0, bf[0], bf[2]);
            mma_f16(acc[1][jp * 2 + 0], a1, bf[0], bf[2]);
            mma_f16(acc[0][jp * 2 + 1], a0, bf[1], bf[3]);
            mma_f16(acc[1][jp * 2 + 1], a1, bf[1], bf[3]);
        }
    }
}

__device__ __forceinline__ void acc_to_zs(float* zs, int wm, int wn, int lane,
                                          float acc[2][4][4])
{
    #pragma unroll
    for (int i = 0; i < 2; i++)
        #pragma unroll
        for (int jj = 0; jj < 4; jj++)
            #pragma unroll
            for (int k4 = 0; k4 < 4; k4++) {
                int r = wm * 32 + i * 16 + (lane >> 2) + ((k4 >> 1) ? 8 : 0);
                int c = wn * 32 + jj * 8 + (lane & 3) * 2 + (k4 & 1);
                zs[r * 132 + c] = acc[i][jj][k4];
            }
}

// ---------------------------------------------------------------------------
// Phase 1: Zpre = X @ W1t^T + bias.  Tile M=64 x N=128, K=320 (5 chunks).
// 512 threads; warps 0-7 compute (32x32 tiles, 2m x 4n), all warps load.
// ---------------------------------------------------------------------------
__global__ void __launch_bounds__(512, 1) phase1_kernel(const float* __restrict__ bias)
{
    extern __shared__ __align__(16) char dsm[];
    const uint32_t raw  = smem_u32(dsm);
    const uint32_t base = (raw + 1023) & ~1023u;
    float* zs = (float*)(dsm + (base - raw));      // reused post-GEMM, pitch 132

    const int tid = threadIdx.x, wid = tid >> 5, lane = tid & 31;
    const int wm = wid >> 2, wn = wid & 3;         // warps 0-7: 2m x 4n
    const int nb = blockIdx.x;
    const size_t r0 = (size_t)blockIdx.y * 64;

    // precomputed ldsm bases
    const uint32_t cxv = ((uint32_t)((lane >> 4) * 16)) ^ ((uint32_t)((lane & 7) * 16));
    const uint32_t a0b = OFF_A + (uint32_t)((wm * 32 + (lane & 15)) * 128);
    const uint32_t a1b = a0b + 16 * 128;
    const uint32_t b0b = OFF_B + (uint32_t)((wn * 32 + (lane & 15)) * 128);
    const uint32_t b1b = b0b + 16 * 128;

    const __half* Ah = g_Xh + r0 * KP1;

    auto load_chunk = [&](int j) {
        uint32_t bp = base + (j & 1) * BUF_SZ;
        int kb = j * 128;
        {
            int row = tid >> 3, q = tid & 7;
            uint32_t so = sw128((uint32_t)(row * 128 + q * 16));
            cpa16(bp + OFF_A + so, (const char*)Ah + (size_t)row * KP1 * 2 + kb + q * 16);
        }
        #pragma unroll
        for (int i = 0; i < 2; i++) {
            int e = tid + i * 512; int c = e >> 3, q = e & 7;
            uint32_t so = sw128((uint32_t)(c * 128 + q * 16));
            cpa16(bp + OFF_B + so,
                  (const char*)g_W1h + (size_t)(nb * 128 + c) * KP1 * 2 + kb + q * 16);
        }
    };

    float acc[2][4][4];
    #pragma unroll
    for (int i = 0; i < 2; i++)
        #pragma unroll
        for (int j = 0; j < 4; j++)
            #pragma unroll
            for (int k = 0; k < 4; k++) acc[i][j][k] = 0.f;

    load_chunk(0); CP_COMMIT();
    for (int j = 0; j < 5; j++) {
        if (j + 1 < 5) { load_chunk(j + 1); CP_COMMIT(); CP_WAIT1(); }
        else           { CP_WAIT0(); }
        __syncthreads();
        if (wid < 8) chunk_mma(base + (j & 1) * BUF_SZ, a0b, a1b, b0b, b1b, cxv, acc);
        __syncthreads();
    }

    if (wid < 8) acc_to_zs(zs, wm, wn, lane, acc);
    __syncthreads();

    int nl = tid & 127, rg = tid >> 7;
    int n0 = nb * 128;
    float bz = bias[n0 + nl];
    #pragma unroll 4
    for (int i = 0; i < 16; i++) {
        int rl = rg * 16 + i;
        g_Zpre[(r0 + rl) * H4 + n0 + nl] = zs[rl * 132 + nl] + bz;
    }
}

// ---------------------------------------------------------------------------
// Persistent step kernel: 128 CTAs (nb 0..63, bm 0..1), all T steps in one
// launch with software grid barriers. c lives in registers; Zpre tile is
// cp.async-prefetched into smem during the GEMM. Warps 0-7 compute.
// ---------------------------------------------------------------------------
__global__ void __launch_bounds__(512, 1) lstm_persistent(float* __restrict__ out)
{
    extern __shared__ __align__(16) char dsm[];
    const uint32_t raw  = smem_u32(dsm);
    const uint32_t base = (raw + 1023) & ~1023u;
    float* zs  = (float*)(dsm + (base - raw));               // pitch 132, post-GEMM
    float* zps = (float*)(dsm + (base - raw) + ZPRE_OFF);    // Zpre stage, pitch 128

    const int tid = threadIdx.x, wid = tid >> 5, lane = tid & 31;
    const int wm = wid >> 2, wn = wid & 3;         // warps 0-7: 2m x 4n
    const int nb = blockIdx.x >> 1;            // 0..63
    const int bm = blockIdx.x & 1;             // 0..1
    const int nl = lane;
    const int n  = nb * 32 + nl;

    // precomputed ldsm bases
    const uint32_t cxv = ((uint32_t)((lane >> 4) * 16)) ^ ((uint32_t)((lane & 7) * 16));
    const uint32_t a0b = OFF_A + (uint32_t)((wm * 32 + (lane & 15)) * 128);
    const uint32_t a1b = a0b + 16 * 128;
    const uint32_t b0b = OFF_B + (uint32_t)((wn * 32 + (lane & 15)) * 128);
    const uint32_t b1b = b0b + 16 * 128;

    // ---- step 0 (no GEMM): c0 = i*g, h0 = o*tanh(c0); seed g_hh[0] ----
    float c_reg[4];
    #pragma unroll
    for (int it = 0; it < 4; it++) {
        int bl = wid + it * 16;
        int b  = bm * 64 + bl;
        const float* zp = g_Zpre + (size_t)b * H4;
        float cn = sigf(zp[n]) * tanhfast(zp[2 * HH + n]);
        float h  = sigf(zp[3 * HH + n]) * tanhfast(cn);
        c_reg[it] = cn;
        out[(size_t)b * TT * HH + n] = h;
        g_hh[0][b * HH + n] = __float2half_rn(h);
    }
    grid_sync();

    for (int t = 1; t < TT; t++) {
        const __half* Ah = g_hh[(t - 1) & 1] + (size_t)bm * 64 * HH;

        auto load_chunk = [&](int j) {
            uint32_t bp = base + (j & 1) * BUF_SZ;
            int kb = j * 128;
            {
                int row = tid >> 3, q = tid & 7;
                uint32_t so = sw128((uint32_t)(row * 128 + q * 16));
                cpa16(bp + OFF_A + so, (const char*)Ah + (size_t)row * HH * 2 + kb + q * 16);
            }
            #pragma unroll
            for (int i = 0; i < 2; i++) {
                int e = tid + i * 512; int c = e >> 3, q = e & 7;
                int ng = (c >> 5) * HH + nb * 32 + (c & 31);   // gate-interleaved
                uint32_t so = sw128((uint32_t)(c * 128 + q * 16));
                cpa16(bp + OFF_B + so, (const char*)g_Whh + (size_t)ng * HH * 2 + kb + q * 16);
            }
        };

        float acc[2][4][4];
        #pragma unroll
        for (int i = 0; i < 2; i++)
            #pragma unroll
            for (int j = 0; j < 4; j++)
                #pragma unroll
                for (int k = 0; k < 4; k++) acc[i][j][k] = 0.f;

        // chunk 0 + Zpre prefetch share the first commit group
        load_chunk(0);
        {
            const char* zsrc = (const char*)g_Zpre;
            #pragma unroll
            for (int i = 0; i < 4; i++) {
                int e = tid + i * 512;
                int row = e >> 5, u = e & 31;                 // u: gate(2b) x q(3b)
                size_t gb = (((size_t)t * BB + bm * 64 + row) * H4
                             + (size_t)(u >> 3) * HH + nb * 32) * 4 + (u & 7) * 16;
                cpa16(base + ZPRE_OFF + (uint32_t)(row * 512 + u * 16), zsrc + gb);
            }
        }
        CP_COMMIT();

        for (int j = 0; j < 32; j++) {
            if (j + 1 < 32) { load_chunk(j + 1); CP_COMMIT(); CP_WAIT1(); }
            else            { CP_WAIT0(); }
            __syncthreads();
            if (wid < 8) chunk_mma(base + (j & 1) * BUF_SZ, a0b, a1b, b0b, b1b, cxv, acc);
            __syncthreads();
        }

        if (wid < 8) acc_to_zs(zs, wm, wn, lane, acc);
        __syncthreads();

        // fused epilogue: smem Zpre + register c
        #pragma unroll
        for (int it = 0; it < 4; it++) {
            int bl = wid + it * 16;
            int b  = bm * 64 + bl;
            const float* zr = zps + bl * 128;
            float vi = zs[bl * 132 +  0 + nl] + zr[ 0 + nl];
            float vf = zs[bl * 132 + 32 + nl] + zr[32 + nl];
            float vg = zs[bl * 132 + 64 + nl] + zr[64 + nl];
            float vo = zs[bl * 132 + 96 + nl] + zr[96 + nl];
            float ig = sigf(vi), fg = sigf(vf);
            float gg = tanhfast(vg), og = sigf(vo);
            float cn = fg * c_reg[it] + ig * gg;
            c_reg[it] = cn;
            float h = og * tanhfast(cn);
            out[(size_t)b * TT * HH + (size_t)t * HH + n] = h;
            g_hh[t & 1][b * HH + n] = __float2half_rn(h);
        }
        grid_sync();
    }
}

// ---------------------------------------------------------------------------
extern "C" void kernel_launch(void* const* d_in, const int* in_sizes, int n_in,
                              void* d_out, int out_size)
{
    (void)in_sizes; (void)n_in; (void)out_size;
    const float* X    = (const float*)d_in[0];   // embed_words [B][T][D]
    const float* W    = (const float*)d_in[2];   // [D+H][4H]  (d_in[1]=lengths unused)
    const float* bias = (const float*)d_in[3];   // [4H]
    float* out        = (float*)d_out;           // [B][T][H]

    cudaFuncSetAttribute(phase1_kernel,   cudaFuncAttributeMaxDynamicSharedMemorySize, SMEM_P1);
    cudaFuncSetAttribute(lstm_persistent, cudaFuncAttributeMaxDynamicSharedMemorySize, SMEM_PERS);

    convert_X<<<TT * BB, KP1>>>(X);
    transW<<<dim3(74, 256), dim3(32, 8)>>>(W);
    phase1_kernel<<<dim3(64, 256), 512, SMEM_P1>>>(bias);
    lstm_persistent<<<128, 512, SMEM_PERS>>>(out);
}